// round 15
// baseline (speedup 1.0000x reference)
#include <cuda_runtime.h>
#include <math.h>

#define NT   45
#define BB   32768
#define HID  64
#define TBL  4096
#define ZPB  16
#define K1_BLOCKS (BB/128)             // 256
#define K3_BLOCKS ((NT*BB)/(256*8))    // 720  (8 elems/thread)
#define TBL_BLOCKS ((TBL + ZPB) / ZPB) // 257
#define TBL4 ((TBL + 4) / 4 + 1)       // 1025 float4 covering TBL+1 entries
#define CTX_SMEM ((NT-1) * 128 * sizeof(float2))   // 45056 B dynamic smem

typedef unsigned long long ull;

// ---------------- device scratch (static, no allocation) ----------------
__device__ float    g_zs[NT*BB];          // latent path
__device__ __align__(16) float g_table[TBL+4];   // P(z) table (+pad for f4 loads)
__device__ unsigned g_zmin_u = 0xFFFFFFFFu;   // reset by k_proj last block
__device__ unsigned g_zmax_u = 0u;
__device__ unsigned g_done   = 0u;        // last-block flag (self-resetting)
__device__ float    g_part_li[K1_BLOCKS];
__device__ float    g_part_kl[K1_BLOCKS];
__device__ float    g_part_logp[K3_BLOCKS];

// monotone float <-> uint mapping for atomicMin/Max on floats
__device__ __forceinline__ unsigned f2ord(float f) {
    unsigned u = __float_as_uint(f);
    return (u & 0x80000000u) ? ~u : (u | 0x80000000u);
}
__device__ __forceinline__ float ord2f(unsigned u) {
    u = (u & 0x80000000u) ? (u ^ 0x80000000u) : ~u;
    return __uint_as_float(u);
}

// ---------------- packed fp32x2 helpers (per-lane IEEE fp32, bit-exact) --
__device__ __forceinline__ ull pack2(float lo, float hi) {
    ull r;
    asm("mov.b64 %0, {%1, %2};" : "=l"(r) : "f"(lo), "f"(hi));
    return r;
}
__device__ __forceinline__ void unpack2(ull v, float& lo, float& hi) {
    asm("mov.b64 {%0, %1}, %2;" : "=f"(lo), "=f"(hi) : "l"(v));
}
__device__ __forceinline__ ull fma2(ull a, ull b, ull c) {
    ull d;
    asm("fma.rn.f32x2 %0, %1, %2, %3;" : "=l"(d) : "l"(a), "l"(b), "l"(c));
    return d;
}
// per-lane relu (compiles to 2x FMNMX; bit-identical to scalar fmaxf)
__device__ __forceinline__ ull relu2(ull v) {
    float lo, hi;
    unpack2(v, lo, hi);
    return pack2(fmaxf(lo, 0.0f), fmaxf(hi, 0.0f));
}

// ---------------- K1: FUSED block-local encoder + posterior + SDE scan ---
// Encoder prologue: identical per-element scalar op sequence as the
// validated standalone k_enc (fma2 lanes are independent IEEE fp32; lanes
// carry 4 consecutive time-steps of the thread's own element). ctx[0] stays
// in registers; ctx[1..44] live in dynamic shared memory (45056 B; total
// static+dynamic 48.7 KB < 48 KB cap... = 48760 <= 49152, fits default).
// Scan recursion: frozen R11 numerics.
__global__ void __launch_bounds__(128) k_scan(
    const float* __restrict__ xs,  const float* __restrict__ ts,
    const float* __restrict__ eps0,const float* __restrict__ bm,
    const float* __restrict__ ew1, const float* __restrict__ eb1,
    const float* __restrict__ ew2, const float* __restrict__ eb2,
    const float* __restrict__ qw,  const float* __restrict__ qb,
    const float* __restrict__ fw1, const float* __restrict__ fb1,
    const float* __restrict__ fw2, const float* __restrict__ fb2,
    const float* __restrict__ pz0m,const float* __restrict__ pz0ls,
    const float* __restrict__ kap, const float* __restrict__ the,
    const float* __restrict__ sig)
{
    extern __shared__ float2 sCtx[];          // [(NT-1)*128] ctx[1..44]

    __shared__ ulonglong2 sE1[HID];   // {w1 splat, b1 splat}
    __shared__ ulonglong2 sE2[HID];   // {u0 splat, u1 splat}
    __shared__ ulonglong2 sWA[32];    // {wz pair, wc0 pair}
    __shared__ ulonglong2 sWB[32];    // {wc1 pair, bias pair}
    __shared__ ulonglong2 sW2d[16];   // {w2 pair 2q, w2 pair 2q+1}
    __shared__ float      sDt[NT];    // dt[n]
    __shared__ float      sSq[NT];    // sqrt(dt[n])
    __shared__ float      sred[4];

    const int t = threadIdx.x;
    if (t < HID) {
        float w1 = ew1[t], b1 = eb1[t], u0 = ew2[2*t], u1 = ew2[2*t+1];
        ulonglong2 e1, e2;
        e1.x = pack2(w1, w1); e1.y = pack2(b1, b1);
        e2.x = pack2(u0, u0); e2.y = pack2(u1, u1);
        sE1[t] = e1; sE2[t] = e2;
    }
    if (t < 32) {
        int p = t;
        ulonglong2 A, B;
        A.x = pack2(fw1[2*p],       fw1[2*p+1]);        // w_z
        A.y = pack2(fw1[HID+2*p],   fw1[HID+2*p+1]);    // w_c0
        B.x = pack2(fw1[2*HID+2*p], fw1[2*HID+2*p+1]);  // w_c1
        B.y = pack2(fb1[2*p],       fb1[2*p+1]);        // bias
        sWA[p] = A; sWB[p] = B;
    }
    if (t < 16) {
        ulonglong2 W;
        W.x = pack2(fw2[4*t],     fw2[4*t+1]);   // pair 2t
        W.y = pack2(fw2[4*t+2],   fw2[4*t+3]);   // pair 2t+1
        sW2d[t] = W;
    }
    if (t < NT - 1) {
        float dt = ts[t+1] - ts[t];
        sDt[t+1] = dt;
        sSq[t+1] = sqrtf(dt);
    }
    __syncthreads();

    const int b = blockIdx.x * 128 + t;
    const float eb0 = eb2[0], eb1v = eb2[1];

    // ---- encoder prologue: ctx[n] for n=1..44 in 11 groups of 4 ----
    #pragma unroll 1
    for (int g = 0; g < 11; g++) {
        const int n0 = 1 + 4 * g;
        float x0 = xs[(n0+0)*BB + b];
        float x1 = xs[(n0+1)*BB + b];
        float x2 = xs[(n0+2)*BB + b];
        float x3 = xs[(n0+3)*BB + b];
        ull xa = pack2(x0, x1);
        ull xb = pack2(x2, x3);
        ull c0a = pack2(eb0, eb0),   c0b = c0a;
        ull c1a = pack2(eb1v, eb1v), c1b = c1a;
        #pragma unroll
        for (int j = 0; j < HID; j++) {
            ulonglong2 E1 = sE1[j], E2 = sE2[j];
            ull ha = relu2(fma2(xa, E1.x, E1.y));
            ull hb = relu2(fma2(xb, E1.x, E1.y));
            c0a = fma2(ha, E2.x, c0a);
            c1a = fma2(ha, E2.y, c1a);
            c0b = fma2(hb, E2.x, c0b);
            c1b = fma2(hb, E2.y, c1b);
        }
        float a0, a1, b0, b1, a2, a3, b2, b3;
        unpack2(c0a, a0, a1); unpack2(c1a, b0, b1);
        unpack2(c0b, a2, a3); unpack2(c1b, b2, b3);
        sCtx[(n0-1+0)*128 + t] = make_float2(a0, b0);
        sCtx[(n0-1+1)*128 + t] = make_float2(a1, b1);
        sCtx[(n0-1+2)*128 + t] = make_float2(a2, b2);
        sCtx[(n0-1+3)*128 + t] = make_float2(a3, b3);
    }

    // ---- ctx[0] in registers (single eval; lane0 carries the value) ----
    float pc0, pc1;
    {
        float x = xs[b];
        ull xa = pack2(x, x);
        ull c0a = pack2(eb0, eb0);
        ull c1a = pack2(eb1v, eb1v);
        #pragma unroll
        for (int j = 0; j < HID; j++) {
            ulonglong2 E1 = sE1[j], E2 = sE2[j];
            ull ha = relu2(fma2(xa, E1.x, E1.y));
            c0a = fma2(ha, E2.x, c0a);
            c1a = fma2(ha, E2.y, c1a);
        }
        float a0, a1, b0, b1;
        unpack2(c0a, a0, a1); unpack2(c1a, b0, b1);
        pc0 = a0; pc1 = b0;
    }
    // no __syncthreads needed: each thread reads only its own sCtx entries

    const float fb2_s = fb2[0];
    const float kappa = kap[0], theta = the[0], sigma = sig[0];
    const float inv_sig = 1.0f / sigma;
    const float pm = pz0m[0], pls = pz0ls[0];

    float qm  = fmaf(pc0, qw[0], fmaf(pc1, qw[2], qb[0]));
    float qls = fmaf(pc0, qw[1], fmaf(pc1, qw[3], qb[1]));

    float z = qm + expf(qls) * eps0[b];

    float dqm = qm - pm;
    float kl  = pls - qls
              + (expf(2.0f*qls) + dqm*dqm) / (2.0f * expf(2.0f*pls))
              - 0.5f;

    g_zs[b] = z;
    float zmn = z, zmx = z;
    float li = 0.0f;

    float bmv = bm[b];

    #pragma unroll 1
    for (int n = 1; n < NT; n++) {
        const float2 cn = sCtx[(n-1)*128 + t];
        const float cc0 = cn.x, cc1 = cn.y, dwe = bmv;
        if (n + 1 < NT) bmv = bm[n*BB + b];
        const float dt = sDt[n], sq = sSq[n];

        const ull zp  = pack2(z,   z);
        const ull c0p = pack2(cc0, cc0);
        const ull c1p = pack2(cc1, cc1);

        ull facc01 = 0ull;   // lanes {f0, f1}
        ull facc23 = 0ull;   // lanes {f2, f3}
        #pragma unroll
        for (int q = 0; q < 16; q++) {
            const ulonglong2 W2 = sW2d[q];
            {
                const int p = 2*q;
                ulonglong2 A = sWA[p], B = sWB[p];
                ull d = fma2(c1p, B.x, B.y);
                d = fma2(c0p, A.y, d);
                d = fma2(zp,  A.x, d);
                facc01 = fma2(relu2(d), W2.x, facc01);
            }
            {
                const int p = 2*q + 1;
                ulonglong2 A = sWA[p], B = sWB[p];
                ull d = fma2(c1p, B.x, B.y);
                d = fma2(c0p, A.y, d);
                d = fma2(zp,  A.x, d);
                facc23 = fma2(relu2(d), W2.y, facc23);
            }
        }
        float f0, f1, f2, f3;
        unpack2(facc01, f0, f1);
        unpack2(facc23, f2, f3);
        float f = fb2_s + ((f0 + f2) + (f1 + f3));   // same association as R9/R11

        float u = (f - kappa * (theta - z)) * inv_sig;
        li = fmaf(0.5f * u * u, dt, li);

        float dw = dwe * sq;
        z = fmaf(f, dt, fmaf(sigma, dw, z));

        g_zs[n*BB + b] = z;
        zmn = fminf(zmn, z);
        zmx = fmaxf(zmx, z);
    }

    // range: order-invariant -> atomics fine
    #pragma unroll
    for (int o = 16; o; o >>= 1) {
        zmn = fminf(zmn, __shfl_xor_sync(0xffffffffu, zmn, o));
        zmx = fmaxf(zmx, __shfl_xor_sync(0xffffffffu, zmx, o));
    }
    if ((t & 31) == 0) {
        atomicMin(&g_zmin_u, f2ord(zmn));
        atomicMax(&g_zmax_u, f2ord(zmx));
    }

    // deterministic fixed-order reductions
    float vli = li, vkl = kl;
    #pragma unroll
    for (int o = 16; o; o >>= 1) {
        vli += __shfl_xor_sync(0xffffffffu, vli, o);
        vkl += __shfl_xor_sync(0xffffffffu, vkl, o);
    }
    int w = t >> 5, l = t & 31;
    if (l == 0) sred[w] = vli;
    __syncthreads();
    if (t == 0) g_part_li[blockIdx.x] = (sred[0]+sred[1])+(sred[2]+sred[3]);
    __syncthreads();
    if (l == 0) sred[w] = vkl;
    __syncthreads();
    if (t == 0) g_part_kl[blockIdx.x] = (sred[0]+sred[1])+(sred[2]+sred[3]);
}

// ---------------- K2: tabulate P(z), 4 lanes cooperate per z-point ------
__global__ void __launch_bounds__(64) k_table(
    const float* __restrict__ pw1, const float* __restrict__ pb1,
    const float* __restrict__ pW2, const float* __restrict__ pb2,
    const float* __restrict__ pw3, const float* __restrict__ pb3)
{
    __shared__ float sw1[HID], sb1[HID], sb2[HID], sw3[HID];
    __shared__ float sW2[HID*HID];
    __shared__ float h1s[ZPB][HID+4];

    const int t = threadIdx.x;   // 64 threads
    { sw1[t]=pw1[t]; sb1[t]=pb1[t]; sb2[t]=pb2[t]; sw3[t]=pw3[t]; }
    for (int i = t; i < HID*HID; i += 64) sW2[i] = pW2[i];
    __syncthreads();

    const int zi    = t >> 2;
    const int lane4 = t & 3;
    const int gz    = blockIdx.x * ZPB + zi;

    float zmin = ord2f(g_zmin_u), zmax = ord2f(g_zmax_u);
    float z = zmin + (zmax - zmin) * ((float)gz / (float)TBL);

    #pragma unroll
    for (int jj = 0; jj < 16; jj++) {
        int j = lane4 * 16 + jj;
        float a = fmaf(z, sw1[j], sb1[j]);
        h1s[zi][j] = fmaxf(a, 0.0f) + __logf(1.0f + __expf(-fabsf(a)));
    }
    __syncthreads();

    const int c0 = lane4 * 16;
    float h2[16];
    #pragma unroll
    for (int k = 0; k < 16; k++) h2[k] = sb2[c0 + k];

    #pragma unroll 8
    for (int j = 0; j < HID; j++) {
        float hj = h1s[zi][j];
        #pragma unroll
        for (int k = 0; k < 16; k++)
            h2[k] = fmaf(hj, sW2[j*HID + c0 + k], h2[k]);
    }

    float acc = 0.0f;
    #pragma unroll
    for (int k = 0; k < 16; k++)
        acc = fmaf(fmaxf(h2[k], 0.0f), sw3[c0 + k], acc);

    acc += __shfl_xor_sync(0xffffffffu, acc, 1);
    acc += __shfl_xor_sync(0xffffffffu, acc, 2);
    if (lane4 == 0 && gz <= TBL) g_table[gz] = acc + pb3[0];
}

// ---------------- K3: smem table lookup -> _xs + logp (x8) + final ------
__global__ void __launch_bounds__(256) k_proj(
    const float* __restrict__ xs, const float* __restrict__ nstd,
    float* __restrict__ out)
{
    __shared__ __align__(16) float sTab[TBL4 * 4];   // 16.4 KB staged table
    const int t = threadIdx.x;

    #pragma unroll
    for (int i = t; i < TBL4; i += 256)
        *(float4*)(sTab + 4*i) = *(const float4*)(g_table + 4*i);
    __syncthreads();

    const int base = (blockIdx.x * 256 + t) * 8;

    float zmin = ord2f(g_zmin_u), zmax = ord2f(g_zmax_u);
    float inv_h = (float)TBL / (zmax - zmin);

    float4 zv0 = *(const float4*)(g_zs + base);
    float4 zv1 = *(const float4*)(g_zs + base + 4);
    float4 xv0 = *(const float4*)(xs + base);
    float4 xv1 = *(const float4*)(xs + base + 4);

    float std = nstd[0];
    float inv_std = 1.0f / std;
    float cterm = -logf(std) - 0.91893853320467274f;

    float zz[8] = {zv0.x, zv0.y, zv0.z, zv0.w, zv1.x, zv1.y, zv1.z, zv1.w};
    float xx[8] = {xv0.x, xv0.y, xv0.z, xv0.w, xv1.x, xv1.y, xv1.z, xv1.w};
    float oo[8];
    float lsum = 0.0f;

    #pragma unroll
    for (int k = 0; k < 8; k++) {
        float tt = (zz[k] - zmin) * inv_h;
        tt = fminf(fmaxf(tt, 0.0f), (float)TBL);
        int   j  = min((int)tt, TBL - 1);
        float fr = tt - (float)j;
        float v0 = sTab[j];
        float v1 = sTab[j+1];
        float xh = fmaf(v1 - v0, fr, v0);
        oo[k] = xh;
        float r = (xx[k] - xh) * inv_std;
        lsum += fmaf(-0.5f, r*r, cterm);
    }

    float2* p = (float2*)(out + 2 + base);   // 8B-aligned
    #pragma unroll
    for (int k = 0; k < 4; k++)
        p[k] = make_float2(oo[2*k], oo[2*k+1]);

    // deterministic block reduce
    float v = lsum;
    #pragma unroll
    for (int o = 16; o; o >>= 1) v += __shfl_xor_sync(0xffffffffu, v, o);
    __shared__ float sred[8];
    __shared__ unsigned sIsLast;
    int w = t >> 5, l = t & 31;
    if (l == 0) sred[w] = v;
    __syncthreads();
    if (t == 0) {
        float s = 0.0f;
        #pragma unroll
        for (int k = 0; k < 8; k++) s += sred[k];
        g_part_logp[blockIdx.x] = s;
        __threadfence();
        unsigned old = atomicAdd(&g_done, 1u);
        sIsLast = (old == (unsigned)(gridDim.x - 1)) ? 1u : 0u;
    }
    __syncthreads();
    if (!sIsLast) return;

    // ---- last block: deterministic final reduction (fixed order) ----
    __shared__ double s[256];

    double a = 0.0;
    for (int i = t; i < K3_BLOCKS; i += 256) a += (double)g_part_logp[i];
    s[t] = a; __syncthreads();
    for (int o = 128; o; o >>= 1) { if (t < o) s[t] += s[t+o]; __syncthreads(); }
    double logp_sum = s[0];
    __syncthreads();

    s[t] = (t < K1_BLOCKS) ? (double)g_part_kl[t] : 0.0; __syncthreads();
    for (int o = 128; o; o >>= 1) { if (t < o) s[t] += s[t+o]; __syncthreads(); }
    double kl_sum = s[0];
    __syncthreads();

    s[t] = (t < K1_BLOCKS) ? (double)g_part_li[t] : 0.0; __syncthreads();
    for (int o = 128; o; o >>= 1) { if (t < o) s[t] += s[t+o]; __syncthreads(); }
    double li_sum = s[0];

    if (t == 0) {
        out[0] = (float)(logp_sum / (double)BB);
        out[1] = (float)((kl_sum + li_sum) / (double)BB);
        // reset all cross-launch state for the next graph replay
        g_done   = 0u;
        g_zmin_u = 0xFFFFFFFFu;
        g_zmax_u = 0u;
    }
}

// ---------------- launch ----------------
extern "C" void kernel_launch(void* const* d_in, const int* in_sizes, int n_in,
                              void* d_out, int out_size)
{
    const float* xs    = (const float*)d_in[0];
    const float* ts    = (const float*)d_in[1];
    const float* nstd  = (const float*)d_in[2];
    const float* eps0  = (const float*)d_in[3];
    const float* bm    = (const float*)d_in[4];
    const float* ew1   = (const float*)d_in[5];
    const float* eb1   = (const float*)d_in[6];
    const float* ew2   = (const float*)d_in[7];
    const float* eb2   = (const float*)d_in[8];
    const float* qw    = (const float*)d_in[9];
    const float* qb    = (const float*)d_in[10];
    const float* fw1   = (const float*)d_in[11];
    const float* fb1   = (const float*)d_in[12];
    const float* fw2   = (const float*)d_in[13];
    const float* fb2   = (const float*)d_in[14];
    const float* pw1   = (const float*)d_in[15];
    const float* pb1   = (const float*)d_in[16];
    const float* pW2   = (const float*)d_in[17];
    const float* pb2   = (const float*)d_in[18];
    const float* pw3   = (const float*)d_in[19];
    const float* pb3   = (const float*)d_in[20];
    const float* pz0m  = (const float*)d_in[21];
    const float* pz0ls = (const float*)d_in[22];
    const float* kap   = (const float*)d_in[23];
    const float* the   = (const float*)d_in[24];
    const float* sig   = (const float*)d_in[25];

    float* out = (float*)d_out;

    k_scan<<<K1_BLOCKS, 128, CTX_SMEM>>>(xs, ts, eps0, bm,
                                         ew1, eb1, ew2, eb2, qw, qb,
                                         fw1, fb1, fw2, fb2,
                                         pz0m, pz0ls, kap, the, sig);
    k_table<<<TBL_BLOCKS, 64>>>(pw1, pb1, pW2, pb2, pw3, pb3);
    k_proj<<<K3_BLOCKS, 256>>>(xs, nstd, out);
}

// round 16
// speedup vs baseline: 1.5114x; 1.5114x over previous
#include <cuda_runtime.h>
#include <math.h>

#define NT   45
#define BB   32768
#define HID  64
#define TBL  4096
#define ZPB  16
#define K1_BLOCKS (BB/128)             // 256
#define KE_BLOCKS ((NT*BB)/(256*4))    // 1440 (4 elems/thread)
#define K3_BLOCKS ((NT*BB)/(256*8))    // 720  (8 elems/thread)
#define TBL_BLOCKS ((TBL + ZPB) / ZPB) // 257
#define TBL4 ((TBL + 4) / 4 + 1)       // 1025 float4 covering TBL+1 entries

typedef unsigned long long ull;

// ---------------- device scratch (static, no allocation) ----------------
__device__ float    g_zs[NT*BB];          // latent path
__device__ float2   g_ctx[NT*BB];         // encoder output (c0,c1)
__device__ __align__(16) float g_table[TBL+4];   // P(z) table (+pad for f4 loads)
__device__ unsigned g_zmin_u = 0xFFFFFFFFu;   // reset by k_proj last block
__device__ unsigned g_zmax_u = 0u;
__device__ unsigned g_done   = 0u;        // last-block flag (self-resetting)
__device__ float    g_part_li[K1_BLOCKS];
__device__ float    g_part_kl[K1_BLOCKS];
__device__ float    g_part_logp[K3_BLOCKS];

// monotone float <-> uint mapping for atomicMin/Max on floats
__device__ __forceinline__ unsigned f2ord(float f) {
    unsigned u = __float_as_uint(f);
    return (u & 0x80000000u) ? ~u : (u | 0x80000000u);
}
__device__ __forceinline__ float ord2f(unsigned u) {
    u = (u & 0x80000000u) ? (u ^ 0x80000000u) : ~u;
    return __uint_as_float(u);
}

// ---------------- packed fp32x2 helpers (per-lane IEEE fp32, bit-exact) --
__device__ __forceinline__ ull pack2(float lo, float hi) {
    ull r;
    asm("mov.b64 %0, {%1, %2};" : "=l"(r) : "f"(lo), "f"(hi));
    return r;
}
__device__ __forceinline__ void unpack2(ull v, float& lo, float& hi) {
    asm("mov.b64 {%0, %1}, %2;" : "=f"(lo), "=f"(hi) : "l"(v));
}
__device__ __forceinline__ ull fma2(ull a, ull b, ull c) {
    ull d;
    asm("fma.rn.f32x2 %0, %1, %2, %3;" : "=l"(d) : "l"(a), "l"(b), "l"(c));
    return d;
}
// per-lane relu (compiles to 2x FMNMX; bit-identical to scalar fmaxf)
__device__ __forceinline__ ull relu2(ull v) {
    float lo, hi;
    unpack2(v, lo, hi);
    return pack2(fmaxf(lo, 0.0f), fmaxf(hi, 0.0f));
}

// ---------------- Ke: encoder, 4 batch elements per thread, f32x2 -------
// (validated R7/R9/R11/R13; per-element op sequence identical to scalar)
__global__ void __launch_bounds__(256) k_enc(
    const float* __restrict__ xs,
    const float* __restrict__ ew1, const float* __restrict__ eb1,
    const float* __restrict__ ew2, const float* __restrict__ eb2)
{
    __shared__ ulonglong2 sE1[HID];   // {w1 splat, b1 splat}
    __shared__ ulonglong2 sE2[HID];   // {w2[:,0] splat, w2[:,1] splat}

    const int t = threadIdx.x;
    if (t < HID) {
        float w1 = ew1[t], b1 = eb1[t], u0 = ew2[2*t], u1 = ew2[2*t+1];
        ulonglong2 e1, e2;
        e1.x = pack2(w1, w1); e1.y = pack2(b1, b1);
        e2.x = pack2(u0, u0); e2.y = pack2(u1, u1);
        sE1[t] = e1; sE2[t] = e2;
    }
    __syncthreads();

    const int idx = (blockIdx.x * 256 + t) * 4;
    float4 xv = *(const float4*)(xs + idx);
    ull xa = pack2(xv.x, xv.y);
    ull xb = pack2(xv.z, xv.w);

    float eb0 = eb2[0], eb1v = eb2[1];
    ull c0a = pack2(eb0, eb0),   c0b = c0a;
    ull c1a = pack2(eb1v, eb1v), c1b = c1a;

    #pragma unroll
    for (int j = 0; j < HID; j++) {
        ulonglong2 E1 = sE1[j], E2 = sE2[j];
        ull ha = relu2(fma2(xa, E1.x, E1.y));
        ull hb = relu2(fma2(xb, E1.x, E1.y));
        c0a = fma2(ha, E2.x, c0a);
        c1a = fma2(ha, E2.y, c1a);
        c0b = fma2(hb, E2.x, c0b);
        c1b = fma2(hb, E2.y, c1b);
    }

    float a0, a1, b0, b1, a2, a3, b2, b3;
    unpack2(c0a, a0, a1); unpack2(c1a, b0, b1);
    unpack2(c0b, a2, a3); unpack2(c1b, b2, b3);
    *(float4*)(g_ctx + idx)     = make_float4(a0, b0, a1, b1);
    *(float4*)(g_ctx + idx + 2) = make_float4(a2, b2, a3, b3);
}

// ---------------- K1: posterior + SDE scan (R13 numerics; n-loop x2) -----
// Only change vs R13: #pragma unroll 2 on the sequential loop — two step
// bodies per iteration let ptxas CSE the loop-invariant weight LDS and
// schedule across the z-dependency. Op sequence per step unchanged.
__global__ void __launch_bounds__(128) k_scan(
    const float* __restrict__ ts,
    const float* __restrict__ eps0,const float* __restrict__ bm,
    const float* __restrict__ qw,  const float* __restrict__ qb,
    const float* __restrict__ fw1, const float* __restrict__ fb1,
    const float* __restrict__ fw2, const float* __restrict__ fb2,
    const float* __restrict__ pz0m,const float* __restrict__ pz0ls,
    const float* __restrict__ kap, const float* __restrict__ the,
    const float* __restrict__ sig)
{
    __shared__ ulonglong2 sWA[32];   // {wz pair, wc0 pair}
    __shared__ ulonglong2 sWB[32];   // {wc1 pair, bias pair}
    __shared__ ulonglong2 sW2d[16];  // {w2 pair 2q, w2 pair 2q+1}
    __shared__ float      sDt[NT];   // dt[n]
    __shared__ float      sSq[NT];   // sqrt(dt[n])
    __shared__ float      sred[4];

    const int t = threadIdx.x;
    if (t < 32) {
        int p = t;
        ulonglong2 A, B;
        A.x = pack2(fw1[2*p],       fw1[2*p+1]);        // w_z
        A.y = pack2(fw1[HID+2*p],   fw1[HID+2*p+1]);    // w_c0
        B.x = pack2(fw1[2*HID+2*p], fw1[2*HID+2*p+1]);  // w_c1
        B.y = pack2(fb1[2*p],       fb1[2*p+1]);        // bias
        sWA[p] = A; sWB[p] = B;
    }
    if (t < 16) {
        ulonglong2 W;
        W.x = pack2(fw2[4*t],     fw2[4*t+1]);   // pair 2t
        W.y = pack2(fw2[4*t+2],   fw2[4*t+3]);   // pair 2t+1
        sW2d[t] = W;
    }
    if (t < NT - 1) {
        float dt = ts[t+1] - ts[t];
        sDt[t+1] = dt;
        sSq[t+1] = sqrtf(dt);
    }
    __syncthreads();

    const int b = blockIdx.x * 128 + t;

    const float fb2_s = fb2[0];
    const float kappa = kap[0], theta = the[0], sigma = sig[0];
    const float inv_sig = 1.0f / sigma;
    const float pm = pz0m[0], pls = pz0ls[0];

    float2 c = g_ctx[b];
    float qm  = fmaf(c.x, qw[0], fmaf(c.y, qw[2], qb[0]));
    float qls = fmaf(c.x, qw[1], fmaf(c.y, qw[3], qb[1]));

    float z = qm + expf(qls) * eps0[b];

    float dqm = qm - pm;
    float kl  = pls - qls
              + (expf(2.0f*qls) + dqm*dqm) / (2.0f * expf(2.0f*pls))
              - 0.5f;

    g_zs[b] = z;
    float zmn = z, zmx = z;
    float li = 0.0f;

    float2 cn  = g_ctx[BB + b];
    float  bmv = bm[b];

    #pragma unroll 2
    for (int n = 1; n < NT; n++) {
        const float cc0 = cn.x, cc1 = cn.y, dwe = bmv;
        if (n + 1 < NT) { cn = g_ctx[(n+1)*BB + b]; bmv = bm[n*BB + b]; }
        const float dt = sDt[n], sq = sSq[n];

        const ull zp  = pack2(z,   z);
        const ull c0p = pack2(cc0, cc0);
        const ull c1p = pack2(cc1, cc1);

        ull facc01 = 0ull;   // lanes {f0, f1}
        ull facc23 = 0ull;   // lanes {f2, f3}
        #pragma unroll
        for (int q = 0; q < 16; q++) {
            const ulonglong2 W2 = sW2d[q];
            {
                const int p = 2*q;
                ulonglong2 A = sWA[p], B = sWB[p];
                ull d = fma2(c1p, B.x, B.y);
                d = fma2(c0p, A.y, d);
                d = fma2(zp,  A.x, d);
                facc01 = fma2(relu2(d), W2.x, facc01);
            }
            {
                const int p = 2*q + 1;
                ulonglong2 A = sWA[p], B = sWB[p];
                ull d = fma2(c1p, B.x, B.y);
                d = fma2(c0p, A.y, d);
                d = fma2(zp,  A.x, d);
                facc23 = fma2(relu2(d), W2.y, facc23);
            }
        }
        float f0, f1, f2, f3;
        unpack2(facc01, f0, f1);
        unpack2(facc23, f2, f3);
        float f = fb2_s + ((f0 + f2) + (f1 + f3));   // same association as R9/R11

        float u = (f - kappa * (theta - z)) * inv_sig;
        li = fmaf(0.5f * u * u, dt, li);

        float dw = dwe * sq;
        z = fmaf(f, dt, fmaf(sigma, dw, z));

        g_zs[n*BB + b] = z;
        zmn = fminf(zmn, z);
        zmx = fmaxf(zmx, z);
    }

    // range: order-invariant -> atomics fine
    #pragma unroll
    for (int o = 16; o; o >>= 1) {
        zmn = fminf(zmn, __shfl_xor_sync(0xffffffffu, zmn, o));
        zmx = fmaxf(zmx, __shfl_xor_sync(0xffffffffu, zmx, o));
    }
    if ((t & 31) == 0) {
        atomicMin(&g_zmin_u, f2ord(zmn));
        atomicMax(&g_zmax_u, f2ord(zmx));
    }

    // deterministic fixed-order reductions
    float vli = li, vkl = kl;
    #pragma unroll
    for (int o = 16; o; o >>= 1) {
        vli += __shfl_xor_sync(0xffffffffu, vli, o);
        vkl += __shfl_xor_sync(0xffffffffu, vkl, o);
    }
    int w = t >> 5, l = t & 31;
    if (l == 0) sred[w] = vli;
    __syncthreads();
    if (t == 0) g_part_li[blockIdx.x] = (sred[0]+sred[1])+(sred[2]+sred[3]);
    __syncthreads();
    if (l == 0) sred[w] = vkl;
    __syncthreads();
    if (t == 0) g_part_kl[blockIdx.x] = (sred[0]+sred[1])+(sred[2]+sred[3]);
}

// ---------------- K2: tabulate P(z), 4 lanes cooperate per z-point ------
__global__ void __launch_bounds__(64) k_table(
    const float* __restrict__ pw1, const float* __restrict__ pb1,
    const float* __restrict__ pW2, const float* __restrict__ pb2,
    const float* __restrict__ pw3, const float* __restrict__ pb3)
{
    __shared__ float sw1[HID], sb1[HID], sb2[HID], sw3[HID];
    __shared__ float sW2[HID*HID];
    __shared__ float h1s[ZPB][HID+4];

    const int t = threadIdx.x;   // 64 threads
    { sw1[t]=pw1[t]; sb1[t]=pb1[t]; sb2[t]=pb2[t]; sw3[t]=pw3[t]; }
    for (int i = t; i < HID*HID; i += 64) sW2[i] = pW2[i];
    __syncthreads();

    const int zi    = t >> 2;
    const int lane4 = t & 3;
    const int gz    = blockIdx.x * ZPB + zi;

    float zmin = ord2f(g_zmin_u), zmax = ord2f(g_zmax_u);
    float z = zmin + (zmax - zmin) * ((float)gz / (float)TBL);

    #pragma unroll
    for (int jj = 0; jj < 16; jj++) {
        int j = lane4 * 16 + jj;
        float a = fmaf(z, sw1[j], sb1[j]);
        h1s[zi][j] = fmaxf(a, 0.0f) + __logf(1.0f + __expf(-fabsf(a)));
    }
    __syncthreads();

    const int c0 = lane4 * 16;
    float h2[16];
    #pragma unroll
    for (int k = 0; k < 16; k++) h2[k] = sb2[c0 + k];

    #pragma unroll 8
    for (int j = 0; j < HID; j++) {
        float hj = h1s[zi][j];
        #pragma unroll
        for (int k = 0; k < 16; k++)
            h2[k] = fmaf(hj, sW2[j*HID + c0 + k], h2[k]);
    }

    float acc = 0.0f;
    #pragma unroll
    for (int k = 0; k < 16; k++)
        acc = fmaf(fmaxf(h2[k], 0.0f), sw3[c0 + k], acc);

    acc += __shfl_xor_sync(0xffffffffu, acc, 1);
    acc += __shfl_xor_sync(0xffffffffu, acc, 2);
    if (lane4 == 0 && gz <= TBL) g_table[gz] = acc + pb3[0];
}

// ---------------- K3: smem table lookup -> _xs + logp (x8) + final ------
__global__ void __launch_bounds__(256) k_proj(
    const float* __restrict__ xs, const float* __restrict__ nstd,
    float* __restrict__ out)
{
    __shared__ __align__(16) float sTab[TBL4 * 4];   // 16.4 KB staged table
    const int t = threadIdx.x;

    #pragma unroll
    for (int i = t; i < TBL4; i += 256)
        *(float4*)(sTab + 4*i) = *(const float4*)(g_table + 4*i);
    __syncthreads();

    const int base = (blockIdx.x * 256 + t) * 8;

    float zmin = ord2f(g_zmin_u), zmax = ord2f(g_zmax_u);
    float inv_h = (float)TBL / (zmax - zmin);

    float4 zv0 = *(const float4*)(g_zs + base);
    float4 zv1 = *(const float4*)(g_zs + base + 4);
    float4 xv0 = *(const float4*)(xs + base);
    float4 xv1 = *(const float4*)(xs + base + 4);

    float std = nstd[0];
    float inv_std = 1.0f / std;
    float cterm = -logf(std) - 0.91893853320467274f;

    float zz[8] = {zv0.x, zv0.y, zv0.z, zv0.w, zv1.x, zv1.y, zv1.z, zv1.w};
    float xx[8] = {xv0.x, xv0.y, xv0.z, xv0.w, xv1.x, xv1.y, xv1.z, xv1.w};
    float oo[8];
    float lsum = 0.0f;

    #pragma unroll
    for (int k = 0; k < 8; k++) {
        float tt = (zz[k] - zmin) * inv_h;
        tt = fminf(fmaxf(tt, 0.0f), (float)TBL);
        int   j  = min((int)tt, TBL - 1);
        float fr = tt - (float)j;
        float v0 = sTab[j];
        float v1 = sTab[j+1];
        float xh = fmaf(v1 - v0, fr, v0);
        oo[k] = xh;
        float r = (xx[k] - xh) * inv_std;
        lsum += fmaf(-0.5f, r*r, cterm);
    }

    float2* p = (float2*)(out + 2 + base);   // 8B-aligned
    #pragma unroll
    for (int k = 0; k < 4; k++)
        p[k] = make_float2(oo[2*k], oo[2*k+1]);

    // deterministic block reduce
    float v = lsum;
    #pragma unroll
    for (int o = 16; o; o >>= 1) v += __shfl_xor_sync(0xffffffffu, v, o);
    __shared__ float sred[8];
    __shared__ unsigned sIsLast;
    int w = t >> 5, l = t & 31;
    if (l == 0) sred[w] = v;
    __syncthreads();
    if (t == 0) {
        float s = 0.0f;
        #pragma unroll
        for (int k = 0; k < 8; k++) s += sred[k];
        g_part_logp[blockIdx.x] = s;
        __threadfence();
        unsigned old = atomicAdd(&g_done, 1u);
        sIsLast = (old == (unsigned)(gridDim.x - 1)) ? 1u : 0u;
    }
    __syncthreads();
    if (!sIsLast) return;

    // ---- last block: deterministic final reduction (fixed order) ----
    __shared__ double s[256];

    double a = 0.0;
    for (int i = t; i < K3_BLOCKS; i += 256) a += (double)g_part_logp[i];
    s[t] = a; __syncthreads();
    for (int o = 128; o; o >>= 1) { if (t < o) s[t] += s[t+o]; __syncthreads(); }
    double logp_sum = s[0];
    __syncthreads();

    s[t] = (t < K1_BLOCKS) ? (double)g_part_kl[t] : 0.0; __syncthreads();
    for (int o = 128; o; o >>= 1) { if (t < o) s[t] += s[t+o]; __syncthreads(); }
    double kl_sum = s[0];
    __syncthreads();

    s[t] = (t < K1_BLOCKS) ? (double)g_part_li[t] : 0.0; __syncthreads();
    for (int o = 128; o; o >>= 1) { if (t < o) s[t] += s[t+o]; __syncthreads(); }
    double li_sum = s[0];

    if (t == 0) {
        out[0] = (float)(logp_sum / (double)BB);
        out[1] = (float)((kl_sum + li_sum) / (double)BB);
        // reset all cross-launch state for the next graph replay
        g_done   = 0u;
        g_zmin_u = 0xFFFFFFFFu;
        g_zmax_u = 0u;
    }
}

// ---------------- launch ----------------
extern "C" void kernel_launch(void* const* d_in, const int* in_sizes, int n_in,
                              void* d_out, int out_size)
{
    const float* xs    = (const float*)d_in[0];
    const float* ts    = (const float*)d_in[1];
    const float* nstd  = (const float*)d_in[2];
    const float* eps0  = (const float*)d_in[3];
    const float* bm    = (const float*)d_in[4];
    const float* ew1   = (const float*)d_in[5];
    const float* eb1   = (const float*)d_in[6];
    const float* ew2   = (const float*)d_in[7];
    const float* eb2   = (const float*)d_in[8];
    const float* qw    = (const float*)d_in[9];
    const float* qb    = (const float*)d_in[10];
    const float* fw1   = (const float*)d_in[11];
    const float* fb1   = (const float*)d_in[12];
    const float* fw2   = (const float*)d_in[13];
    const float* fb2   = (const float*)d_in[14];
    const float* pw1   = (const float*)d_in[15];
    const float* pb1   = (const float*)d_in[16];
    const float* pW2   = (const float*)d_in[17];
    const float* pb2   = (const float*)d_in[18];
    const float* pw3   = (const float*)d_in[19];
    const float* pb3   = (const float*)d_in[20];
    const float* pz0m  = (const float*)d_in[21];
    const float* pz0ls = (const float*)d_in[22];
    const float* kap   = (const float*)d_in[23];
    const float* the   = (const float*)d_in[24];
    const float* sig   = (const float*)d_in[25];

    float* out = (float*)d_out;

    k_enc<<<KE_BLOCKS, 256>>>(xs, ew1, eb1, ew2, eb2);
    k_scan<<<K1_BLOCKS, 128>>>(ts, eps0, bm, qw, qb,
                               fw1, fb1, fw2, fb2,
                               pz0m, pz0ls, kap, the, sig);
    k_table<<<TBL_BLOCKS, 64>>>(pw1, pb1, pW2, pb2, pw3, pb3);
    k_proj<<<K3_BLOCKS, 256>>>(xs, nstd, out);
}

// round 17
// speedup vs baseline: 2.0108x; 1.3304x over previous
#include <cuda_runtime.h>
#include <math.h>

#define NT   45
#define BB   32768
#define HID  64
#define TBL  2048
#define ZPB  16
#define K1_BLOCKS (BB/128)             // 256
#define KE_BLOCKS ((NT*BB)/(256*4))    // 1440 (4 elems/thread)
#define K3_BLOCKS ((NT*BB)/(256*8))    // 720  (8 elems/thread)
#define TBL_BLOCKS ((TBL + ZPB) / ZPB) // 129

typedef unsigned long long ull;

// ---------------- device scratch (static, no allocation) ----------------
__device__ float    g_zs[NT*BB];          // latent path
__device__ float2   g_ctx[NT*BB];         // encoder output (c0,c1)
__device__ __align__(16) float g_table[TBL+4];   // P(z) lookup table
__device__ unsigned g_zmin_u = 0xFFFFFFFFu;   // reset by k_final each launch
__device__ unsigned g_zmax_u = 0u;
__device__ float    g_part_li[K1_BLOCKS];
__device__ float    g_part_kl[K1_BLOCKS];
__device__ float    g_part_logp[K3_BLOCKS];

// monotone float <-> uint mapping for atomicMin/Max on floats
__device__ __forceinline__ unsigned f2ord(float f) {
    unsigned u = __float_as_uint(f);
    return (u & 0x80000000u) ? ~u : (u | 0x80000000u);
}
__device__ __forceinline__ float ord2f(unsigned u) {
    u = (u & 0x80000000u) ? (u ^ 0x80000000u) : ~u;
    return __uint_as_float(u);
}

// ---------------- packed fp32x2 helpers (per-lane IEEE fp32, bit-exact) --
__device__ __forceinline__ ull pack2(float lo, float hi) {
    ull r;
    asm("mov.b64 %0, {%1, %2};" : "=l"(r) : "f"(lo), "f"(hi));
    return r;
}
__device__ __forceinline__ void unpack2(ull v, float& lo, float& hi) {
    asm("mov.b64 {%0, %1}, %2;" : "=f"(lo), "=f"(hi) : "l"(v));
}
__device__ __forceinline__ ull fma2(ull a, ull b, ull c) {
    ull d;
    asm("fma.rn.f32x2 %0, %1, %2, %3;" : "=l"(d) : "l"(a), "l"(b), "l"(c));
    return d;
}
// per-lane relu (compiles to 2x FMNMX; bit-identical to scalar fmaxf)
__device__ __forceinline__ ull relu2(ull v) {
    float lo, hi;
    unpack2(v, lo, hi);
    return pack2(fmaxf(lo, 0.0f), fmaxf(hi, 0.0f));
}

// ---------------- Ke: encoder, 4 batch elements per thread, f32x2 -------
// (validated R7/R9/R11/R13; per-element op sequence identical to scalar)
__global__ void __launch_bounds__(256) k_enc(
    const float* __restrict__ xs,
    const float* __restrict__ ew1, const float* __restrict__ eb1,
    const float* __restrict__ ew2, const float* __restrict__ eb2)
{
    __shared__ ulonglong2 sE1[HID];   // {w1 splat, b1 splat}
    __shared__ ulonglong2 sE2[HID];   // {w2[:,0] splat, w2[:,1] splat}

    const int t = threadIdx.x;
    if (t < HID) {
        float w1 = ew1[t], b1 = eb1[t], u0 = ew2[2*t], u1 = ew2[2*t+1];
        ulonglong2 e1, e2;
        e1.x = pack2(w1, w1); e1.y = pack2(b1, b1);
        e2.x = pack2(u0, u0); e2.y = pack2(u1, u1);
        sE1[t] = e1; sE2[t] = e2;
    }
    __syncthreads();

    const int idx = (blockIdx.x * 256 + t) * 4;
    float4 xv = *(const float4*)(xs + idx);
    ull xa = pack2(xv.x, xv.y);
    ull xb = pack2(xv.z, xv.w);

    float eb0 = eb2[0], eb1v = eb2[1];
    ull c0a = pack2(eb0, eb0),   c0b = c0a;
    ull c1a = pack2(eb1v, eb1v), c1b = c1a;

    #pragma unroll
    for (int j = 0; j < HID; j++) {
        ulonglong2 E1 = sE1[j], E2 = sE2[j];
        ull ha = relu2(fma2(xa, E1.x, E1.y));
        ull hb = relu2(fma2(xb, E1.x, E1.y));
        c0a = fma2(ha, E2.x, c0a);
        c1a = fma2(ha, E2.y, c1a);
        c0b = fma2(hb, E2.x, c0b);
        c1b = fma2(hb, E2.y, c1b);
    }

    float a0, a1, b0, b1, a2, a3, b2, b3;
    unpack2(c0a, a0, a1); unpack2(c1a, b0, b1);
    unpack2(c0b, a2, a3); unpack2(c1b, b2, b3);
    *(float4*)(g_ctx + idx)     = make_float4(a0, b0, a1, b1);
    *(float4*)(g_ctx + idx + 2) = make_float4(a2, b2, a3, b3);
}

// ---------------- K1: posterior + SDE scan (R13 frozen, bit-identical) ---
__global__ void __launch_bounds__(128) k_scan(
    const float* __restrict__ ts,
    const float* __restrict__ eps0,const float* __restrict__ bm,
    const float* __restrict__ qw,  const float* __restrict__ qb,
    const float* __restrict__ fw1, const float* __restrict__ fb1,
    const float* __restrict__ fw2, const float* __restrict__ fb2,
    const float* __restrict__ pz0m,const float* __restrict__ pz0ls,
    const float* __restrict__ kap, const float* __restrict__ the,
    const float* __restrict__ sig)
{
    __shared__ ulonglong2 sWA[32];   // {wz pair, wc0 pair}
    __shared__ ulonglong2 sWB[32];   // {wc1 pair, bias pair}
    __shared__ ulonglong2 sW2d[16];  // {w2 pair 2q, w2 pair 2q+1}
    __shared__ float      sDt[NT];   // dt[n]
    __shared__ float      sSq[NT];   // sqrt(dt[n])
    __shared__ float      sred[4];

    const int t = threadIdx.x;
    if (t < 32) {
        int p = t;
        ulonglong2 A, B;
        A.x = pack2(fw1[2*p],       fw1[2*p+1]);        // w_z
        A.y = pack2(fw1[HID+2*p],   fw1[HID+2*p+1]);    // w_c0
        B.x = pack2(fw1[2*HID+2*p], fw1[2*HID+2*p+1]);  // w_c1
        B.y = pack2(fb1[2*p],       fb1[2*p+1]);        // bias
        sWA[p] = A; sWB[p] = B;
    }
    if (t < 16) {
        ulonglong2 W;
        W.x = pack2(fw2[4*t],     fw2[4*t+1]);   // pair 2t
        W.y = pack2(fw2[4*t+2],   fw2[4*t+3]);   // pair 2t+1
        sW2d[t] = W;
    }
    if (t < NT - 1) {
        float dt = ts[t+1] - ts[t];
        sDt[t+1] = dt;
        sSq[t+1] = sqrtf(dt);
    }
    __syncthreads();

    const int b = blockIdx.x * 128 + t;

    const float fb2_s = fb2[0];
    const float kappa = kap[0], theta = the[0], sigma = sig[0];
    const float inv_sig = 1.0f / sigma;
    const float pm = pz0m[0], pls = pz0ls[0];

    float2 c = g_ctx[b];
    float qm  = fmaf(c.x, qw[0], fmaf(c.y, qw[2], qb[0]));
    float qls = fmaf(c.x, qw[1], fmaf(c.y, qw[3], qb[1]));

    float z = qm + expf(qls) * eps0[b];

    float dqm = qm - pm;
    float kl  = pls - qls
              + (expf(2.0f*qls) + dqm*dqm) / (2.0f * expf(2.0f*pls))
              - 0.5f;

    g_zs[b] = z;
    float zmn = z, zmx = z;
    float li = 0.0f;

    float2 cn  = g_ctx[BB + b];
    float  bmv = bm[b];

    #pragma unroll 1
    for (int n = 1; n < NT; n++) {
        const float cc0 = cn.x, cc1 = cn.y, dwe = bmv;
        if (n + 1 < NT) { cn = g_ctx[(n+1)*BB + b]; bmv = bm[n*BB + b]; }
        const float dt = sDt[n], sq = sSq[n];

        const ull zp  = pack2(z,   z);
        const ull c0p = pack2(cc0, cc0);
        const ull c1p = pack2(cc1, cc1);

        ull facc01 = 0ull;   // lanes {f0, f1}
        ull facc23 = 0ull;   // lanes {f2, f3}
        #pragma unroll
        for (int q = 0; q < 16; q++) {
            const ulonglong2 W2 = sW2d[q];
            {
                const int p = 2*q;
                ulonglong2 A = sWA[p], B = sWB[p];
                ull d = fma2(c1p, B.x, B.y);
                d = fma2(c0p, A.y, d);
                d = fma2(zp,  A.x, d);
                facc01 = fma2(relu2(d), W2.x, facc01);
            }
            {
                const int p = 2*q + 1;
                ulonglong2 A = sWA[p], B = sWB[p];
                ull d = fma2(c1p, B.x, B.y);
                d = fma2(c0p, A.y, d);
                d = fma2(zp,  A.x, d);
                facc23 = fma2(relu2(d), W2.y, facc23);
            }
        }
        float f0, f1, f2, f3;
        unpack2(facc01, f0, f1);
        unpack2(facc23, f2, f3);
        float f = fb2_s + ((f0 + f2) + (f1 + f3));   // same association as R9/R11

        float u = (f - kappa * (theta - z)) * inv_sig;
        li = fmaf(0.5f * u * u, dt, li);

        float dw = dwe * sq;
        z = fmaf(f, dt, fmaf(sigma, dw, z));

        g_zs[n*BB + b] = z;
        zmn = fminf(zmn, z);
        zmx = fmaxf(zmx, z);
    }

    // range: order-invariant -> atomics fine
    #pragma unroll
    for (int o = 16; o; o >>= 1) {
        zmn = fminf(zmn, __shfl_xor_sync(0xffffffffu, zmn, o));
        zmx = fmaxf(zmx, __shfl_xor_sync(0xffffffffu, zmx, o));
    }
    if ((t & 31) == 0) {
        atomicMin(&g_zmin_u, f2ord(zmn));
        atomicMax(&g_zmax_u, f2ord(zmx));
    }

    // deterministic fixed-order reductions
    float vli = li, vkl = kl;
    #pragma unroll
    for (int o = 16; o; o >>= 1) {
        vli += __shfl_xor_sync(0xffffffffu, vli, o);
        vkl += __shfl_xor_sync(0xffffffffu, vkl, o);
    }
    int w = t >> 5, l = t & 31;
    if (l == 0) sred[w] = vli;
    __syncthreads();
    if (t == 0) g_part_li[blockIdx.x] = (sred[0]+sred[1])+(sred[2]+sred[3]);
    __syncthreads();
    if (l == 0) sred[w] = vkl;
    __syncthreads();
    if (t == 0) g_part_kl[blockIdx.x] = (sred[0]+sred[1])+(sred[2]+sred[3]);
}

// ---------------- K2: tabulate P(z), 4 lanes cooperate per z-point ------
__global__ void __launch_bounds__(64) k_table(
    const float* __restrict__ pw1, const float* __restrict__ pb1,
    const float* __restrict__ pW2, const float* __restrict__ pb2,
    const float* __restrict__ pw3, const float* __restrict__ pb3)
{
    __shared__ float sw1[HID], sb1[HID], sb2[HID], sw3[HID];
    __shared__ float sW2[HID*HID];
    __shared__ float h1s[ZPB][HID+4];

    const int t = threadIdx.x;   // 64 threads
    { sw1[t]=pw1[t]; sb1[t]=pb1[t]; sb2[t]=pb2[t]; sw3[t]=pw3[t]; }
    for (int i = t; i < HID*HID; i += 64) sW2[i] = pW2[i];
    __syncthreads();

    const int zi    = t >> 2;
    const int lane4 = t & 3;
    const int gz    = blockIdx.x * ZPB + zi;

    float zmin = ord2f(g_zmin_u), zmax = ord2f(g_zmax_u);
    float z = zmin + (zmax - zmin) * ((float)gz / (float)TBL);

    #pragma unroll
    for (int jj = 0; jj < 16; jj++) {
        int j = lane4 * 16 + jj;
        float a = fmaf(z, sw1[j], sb1[j]);
        h1s[zi][j] = fmaxf(a, 0.0f) + __logf(1.0f + __expf(-fabsf(a)));
    }
    __syncthreads();

    const int c0 = lane4 * 16;
    float h2[16];
    #pragma unroll
    for (int k = 0; k < 16; k++) h2[k] = sb2[c0 + k];

    #pragma unroll 8
    for (int j = 0; j < HID; j++) {
        float hj = h1s[zi][j];
        #pragma unroll
        for (int k = 0; k < 16; k++)
            h2[k] = fmaf(hj, sW2[j*HID + c0 + k], h2[k]);
    }

    float acc = 0.0f;
    #pragma unroll
    for (int k = 0; k < 16; k++)
        acc = fmaf(fmaxf(h2[k], 0.0f), sw3[c0 + k], acc);

    acc += __shfl_xor_sync(0xffffffffu, acc, 1);
    acc += __shfl_xor_sync(0xffffffffu, acc, 2);
    if (lane4 == 0 && gz <= TBL) g_table[gz] = acc + pb3[0];
}

// ---------------- K3: table lookup -> _xs + logp (x8, R7 shape) ---------
__global__ void __launch_bounds__(256) k_proj(
    const float* __restrict__ xs, const float* __restrict__ nstd,
    float* __restrict__ out)
{
    const int base = (blockIdx.x * 256 + threadIdx.x) * 8;

    float zmin = ord2f(g_zmin_u), zmax = ord2f(g_zmax_u);
    float inv_h = (float)TBL / (zmax - zmin);

    float4 zv0 = *(const float4*)(g_zs + base);
    float4 zv1 = *(const float4*)(g_zs + base + 4);
    float4 xv0 = *(const float4*)(xs + base);
    float4 xv1 = *(const float4*)(xs + base + 4);

    float std = nstd[0];
    float inv_std = 1.0f / std;
    float cterm = -logf(std) - 0.91893853320467274f;

    float zz[8] = {zv0.x, zv0.y, zv0.z, zv0.w, zv1.x, zv1.y, zv1.z, zv1.w};
    float xx[8] = {xv0.x, xv0.y, xv0.z, xv0.w, xv1.x, xv1.y, xv1.z, xv1.w};
    float oo[8];
    float lsum = 0.0f;

    #pragma unroll
    for (int k = 0; k < 8; k++) {
        float tt = (zz[k] - zmin) * inv_h;
        tt = fminf(fmaxf(tt, 0.0f), (float)TBL);
        int   j  = min((int)tt, TBL - 1);
        float fr = tt - (float)j;
        float v0 = g_table[j];
        float v1 = g_table[j+1];
        float xh = fmaf(v1 - v0, fr, v0);
        oo[k] = xh;
        float r = (xx[k] - xh) * inv_std;
        lsum += fmaf(-0.5f, r*r, cterm);
    }

    float2* p = (float2*)(out + 2 + base);   // 8B-aligned
    #pragma unroll
    for (int k = 0; k < 4; k++)
        p[k] = make_float2(oo[2*k], oo[2*k+1]);

    // deterministic block reduce
    float v = lsum;
    #pragma unroll
    for (int o = 16; o; o >>= 1) v += __shfl_xor_sync(0xffffffffu, v, o);
    __shared__ float sred[8];
    int w = threadIdx.x >> 5, l = threadIdx.x & 31;
    if (l == 0) sred[w] = v;
    __syncthreads();
    if (threadIdx.x == 0) {
        float s = 0.0f;
        #pragma unroll
        for (int k = 0; k < 8; k++) s += sred[k];
        g_part_logp[blockIdx.x] = s;
    }
}

// ---------------- K4: final reduction + state reset for next launch -----
__global__ void __launch_bounds__(256) k_final(float* __restrict__ out)
{
    __shared__ double s[256];
    const int t = threadIdx.x;

    double a = 0.0;
    for (int i = t; i < K3_BLOCKS; i += 256) a += (double)g_part_logp[i];
    s[t] = a; __syncthreads();
    for (int o = 128; o; o >>= 1) { if (t < o) s[t] += s[t+o]; __syncthreads(); }
    double logp_sum = s[0];
    __syncthreads();

    s[t] = (t < K1_BLOCKS) ? (double)g_part_kl[t] : 0.0; __syncthreads();
    for (int o = 128; o; o >>= 1) { if (t < o) s[t] += s[t+o]; __syncthreads(); }
    double kl_sum = s[0];
    __syncthreads();

    s[t] = (t < K1_BLOCKS) ? (double)g_part_li[t] : 0.0; __syncthreads();
    for (int o = 128; o; o >>= 1) { if (t < o) s[t] += s[t+o]; __syncthreads(); }
    double li_sum = s[0];

    if (t == 0) {
        out[0] = (float)(logp_sum / (double)BB);
        out[1] = (float)((kl_sum + li_sum) / (double)BB);
        // reset min/max state for the next (replayed) launch
        g_zmin_u = 0xFFFFFFFFu;
        g_zmax_u = 0u;
    }
}

// ---------------- launch ----------------
extern "C" void kernel_launch(void* const* d_in, const int* in_sizes, int n_in,
                              void* d_out, int out_size)
{
    const float* xs    = (const float*)d_in[0];
    const float* ts    = (const float*)d_in[1];
    const float* nstd  = (const float*)d_in[2];
    const float* eps0  = (const float*)d_in[3];
    const float* bm    = (const float*)d_in[4];
    const float* ew1   = (const float*)d_in[5];
    const float* eb1   = (const float*)d_in[6];
    const float* ew2   = (const float*)d_in[7];
    const float* eb2   = (const float*)d_in[8];
    const float* qw    = (const float*)d_in[9];
    const float* qb    = (const float*)d_in[10];
    const float* fw1   = (const float*)d_in[11];
    const float* fb1   = (const float*)d_in[12];
    const float* fw2   = (const float*)d_in[13];
    const float* fb2   = (const float*)d_in[14];
    const float* pw1   = (const float*)d_in[15];
    const float* pb1   = (const float*)d_in[16];
    const float* pW2   = (const float*)d_in[17];
    const float* pb2   = (const float*)d_in[18];
    const float* pw3   = (const float*)d_in[19];
    const float* pb3   = (const float*)d_in[20];
    const float* pz0m  = (const float*)d_in[21];
    const float* pz0ls = (const float*)d_in[22];
    const float* kap   = (const float*)d_in[23];
    const float* the   = (const float*)d_in[24];
    const float* sig   = (const float*)d_in[25];

    float* out = (float*)d_out;

    k_enc<<<KE_BLOCKS, 256>>>(xs, ew1, eb1, ew2, eb2);
    k_scan<<<K1_BLOCKS, 128>>>(ts, eps0, bm, qw, qb,
                               fw1, fb1, fw2, fb2,
                               pz0m, pz0ls, kap, the, sig);
    k_table<<<TBL_BLOCKS, 64>>>(pw1, pb1, pW2, pb2, pw3, pb3);
    k_proj<<<K3_BLOCKS, 256>>>(xs, nstd, out);
    k_final<<<1, 256>>>(out);
}